// round 1
// baseline (speedup 1.0000x reference)
#include <cuda_runtime.h>
#include <cuda_bf16.h>
#include <math.h>

// Problem constants
#define B_  512
#define S_  512
#define DI_ 256
#define DO_ 256

// ---------------- helpers ----------------

__device__ __forceinline__ void cpasync16(void* smem_dst, const void* gsrc) {
    unsigned saddr = (unsigned)__cvta_generic_to_shared(smem_dst);
    asm volatile("cp.async.cg.shared.global [%0], [%1], 16;\n" :: "r"(saddr), "l"(gsrc));
}
__device__ __forceinline__ void cp_commit() {
    asm volatile("cp.async.commit_group;\n");
}
template <int N>
__device__ __forceinline__ void cp_wait() {
    asm volatile("cp.async.wait_group %0;\n" :: "n"(N));
}

__device__ __forceinline__ void mma_tf32(float c[4],
                                         unsigned a0, unsigned a1, unsigned a2, unsigned a3,
                                         unsigned b0, unsigned b1) {
    asm volatile(
        "mma.sync.aligned.m16n8k8.row.col.f32.tf32.tf32.f32 "
        "{%0,%1,%2,%3}, {%4,%5,%6,%7}, {%8,%9}, {%0,%1,%2,%3};\n"
        : "+f"(c[0]), "+f"(c[1]), "+f"(c[2]), "+f"(c[3])
        : "r"(a0), "r"(a1), "r"(a2), "r"(a3), "r"(b0), "r"(b1));
}

__device__ __forceinline__ unsigned f2u(float f) { return __float_as_uint(f); }

// ---------------- Phase 1: Z[b,t,:] = x[b,t,:] @ Wx[t]  (written into d_out) ----------------
// Grid: (n_tiles=2, m_tiles=4, t=512). CTA tile: M=128 (batch) x N=128, K=256 in 8 chunks of 32.
// 8 warps: warp_m = warp&3 (32 rows each), warp_n = warp>>2 (64 cols each). Warp tile 32x64.

#define P1_AS  (128 * 36)   // padded stride 36 floats (144B, 16B-aligned, conflict-free frags)
#define P1_BS  (32 * 132)   // padded stride 132 floats (528B)
#define P1_SMEM ((2 * P1_AS + 2 * P1_BS) * 4)

__global__ __launch_bounds__(256, 1) void rnn_phase1(
    const float* __restrict__ x, const float* __restrict__ Wx, float* __restrict__ out)
{
    extern __shared__ float sm[];
    float* As[2] = { sm, sm + P1_AS };
    float* Bs[2] = { sm + 2 * P1_AS, sm + 2 * P1_AS + P1_BS };

    const int t      = blockIdx.z;
    const int m_base = blockIdx.y * 128;
    const int n_base = blockIdx.x * 128;
    const int tid    = threadIdx.x;
    const int warp   = tid >> 5, lane = tid & 31;
    const int wm     = warp & 3, wn = warp >> 2;
    const int grp    = lane >> 2, tig = lane & 3;

    float acc[2][8][4];
#pragma unroll
    for (int mt = 0; mt < 2; mt++)
#pragma unroll
        for (int nt = 0; nt < 8; nt++)
#pragma unroll
            for (int i = 0; i < 4; i++) acc[mt][nt][i] = 0.f;

    // chunk loaders: 32 k-columns per chunk
    auto loadA = [&](int kc, int buf) {
#pragma unroll
        for (int j = 0; j < 4; j++) {
            int i = tid + j * 256;
            int r = i >> 3, q = i & 7;          // 8 float4 per row of 32 floats
            cpasync16(&As[buf][r * 36 + q * 4],
                      x + ((m_base + r) * S_ + t) * DI_ + kc * 32 + q * 4);
        }
        cp_commit();
    };
    auto loadB = [&](int kc, int buf) {
#pragma unroll
        for (int j = 0; j < 4; j++) {
            int i = tid + j * 256;
            int k = i >> 5, q = i & 31;         // 32 float4 per row of 128 floats
            cpasync16(&Bs[buf][k * 132 + q * 4],
                      Wx + t * (DI_ * DO_) + (kc * 32 + k) * DO_ + n_base + q * 4);
        }
        cp_commit();
    };

    loadA(0, 0); loadB(0, 0);
    loadA(1, 1); loadB(1, 1);

    for (int kc = 0; kc < 8; kc++) {
        if (kc < 7) cp_wait<2>(); else cp_wait<0>();   // each chunk = 2 groups (A,B)
        __syncthreads();
        const int buf = kc & 1;
        const float* A = As[buf];
        const float* Bsm = Bs[buf];
#pragma unroll
        for (int ks = 0; ks < 4; ks++) {
            const int k = ks * 8;
            unsigned a[2][4];
#pragma unroll
            for (int mt = 0; mt < 2; mt++) {
                const int rb = wm * 32 + mt * 16;
                a[mt][0] = f2u(A[(rb + grp)     * 36 + k + tig]);
                a[mt][1] = f2u(A[(rb + grp + 8) * 36 + k + tig]);
                a[mt][2] = f2u(A[(rb + grp)     * 36 + k + 4 + tig]);
                a[mt][3] = f2u(A[(rb + grp + 8) * 36 + k + 4 + tig]);
            }
#pragma unroll
            for (int nt = 0; nt < 8; nt++) {
                const int cb = wn * 64 + nt * 8 + grp;
                unsigned b0 = f2u(Bsm[(k + tig)     * 132 + cb]);
                unsigned b1 = f2u(Bsm[(k + 4 + tig) * 132 + cb]);
#pragma unroll
                for (int mt = 0; mt < 2; mt++)
                    mma_tf32(acc[mt][nt], a[mt][0], a[mt][1], a[mt][2], a[mt][3], b0, b1);
            }
        }
        __syncthreads();
        if (kc + 2 < 8) { loadA(kc + 2, buf); loadB(kc + 2, buf); }
    }

    // epilogue: write Z to out[b][t][n]
#pragma unroll
    for (int mt = 0; mt < 2; mt++) {
#pragma unroll
        for (int nt = 0; nt < 8; nt++) {
            const int row = m_base + wm * 32 + mt * 16 + grp;
            const int col = n_base + wn * 64 + nt * 8 + 2 * tig;
            const int g0 = (row * S_ + t) * DO_ + col;
            float2 v0; v0.x = acc[mt][nt][0]; v0.y = acc[mt][nt][1];
            *(float2*)&out[g0] = v0;
            const int g1 = ((row + 8) * S_ + t) * DO_ + col;
            float2 v1; v1.x = acc[mt][nt][2]; v1.y = acc[mt][nt][3];
            *(float2*)&out[g1] = v1;
        }
    }
}

// ---------------- Phase 2: recurrence h_t = tanh(Z_t + h_{t-1} @ Wh[t]) ----------------
// 32 persistent CTAs, each owns a 16-row batch slice for all 512 steps. No inter-CTA sync.
// Per step: stream Wh[t] (256KB) through smem in 4 chunks of 64 K-rows (double-buffered
// cp.async). h kept in smem (16x256), accum in registers, mma tf32.
// 8 warps: warp w owns output cols [w*32, w*32+32). Reads Z from out, overwrites with h.

#define P2_HS   (16 * 260)          // h: stride 260 floats (1040B aligned, conflict-free)
#define P2_WS   (64 * 260)          // Wh chunk
#define P2_SMEM ((P2_HS + 2 * P2_WS) * 4)

__global__ __launch_bounds__(256, 1) void rnn_phase2(
    const float* __restrict__ Wh, float* __restrict__ out)
{
    extern __shared__ float sm[];
    float* hs = sm;
    float* Ws[2] = { sm + P2_HS, sm + P2_HS + P2_WS };

    const int tid  = threadIdx.x;
    const int warp = tid >> 5, lane = tid & 31;
    const int grp  = lane >> 2, tig = lane & 3;
    const int brow = blockIdx.x * 16;

    // h_{-1} = 0
    for (int i = tid; i < P2_HS; i += 256) hs[i] = 0.f;
    __syncthreads();

    auto loadW = [&](int t, int kc, int buf) {
        const float* src = Wh + t * (DO_ * DO_) + kc * 64 * DO_;
        float* dst = Ws[buf];
#pragma unroll
        for (int j = 0; j < 16; j++) {
            int i = tid + j * 256;
            int k = i >> 6, q = i & 63;         // 64 float4 per 256-float row
            cpasync16(&dst[k * 260 + q * 4], src + k * DO_ + q * 4);
        }
        cp_commit();
    };

    for (int t = 0; t < S_; t++) {
        float acc[4][4];
#pragma unroll
        for (int nt = 0; nt < 4; nt++)
#pragma unroll
            for (int i = 0; i < 4; i++) acc[nt][i] = 0.f;

        loadW(t, 0, 0);
        loadW(t, 1, 1);

        for (int kc = 0; kc < 4; kc++) {
            if (kc < 3) cp_wait<1>(); else cp_wait<0>();
            __syncthreads();
            const float* W = Ws[kc & 1];
            const int kbase = kc * 64;
#pragma unroll
            for (int ks = 0; ks < 8; ks++) {
                const int k = ks * 8;
                unsigned a0 = f2u(hs[(grp)     * 260 + kbase + k + tig]);
                unsigned a1 = f2u(hs[(grp + 8) * 260 + kbase + k + tig]);
                unsigned a2 = f2u(hs[(grp)     * 260 + kbase + k + 4 + tig]);
                unsigned a3 = f2u(hs[(grp + 8) * 260 + kbase + k + 4 + tig]);
#pragma unroll
                for (int nt = 0; nt < 4; nt++) {
                    const int cb = warp * 32 + nt * 8 + grp;
                    unsigned b0 = f2u(W[(k + tig)     * 260 + cb]);
                    unsigned b1 = f2u(W[(k + 4 + tig) * 260 + cb]);
                    mma_tf32(acc[nt], a0, a1, a2, a3, b0, b1);
                }
            }
            __syncthreads();
            if (kc + 2 < 4) loadW(t, kc + 2, kc & 1);
        }

        // epilogue: h = tanh(Z + h@Wh); overwrite Z in gmem, refresh h in smem
#pragma unroll
        for (int nt = 0; nt < 4; nt++) {
            const int col = warp * 32 + nt * 8 + 2 * tig;
            const int r0 = brow + grp;
            const int g0 = (r0 * S_ + t) * DO_ + col;
            float2 z0 = *(const float2*)&out[g0];
            float2 h0;
            h0.x = tanhf(z0.x + acc[nt][0]);
            h0.y = tanhf(z0.y + acc[nt][1]);
            *(float2*)&out[g0] = h0;
            hs[grp * 260 + col] = h0.x;
            hs[grp * 260 + col + 1] = h0.y;

            const int r1 = r0 + 8;
            const int g1 = (r1 * S_ + t) * DO_ + col;
            float2 z1 = *(const float2*)&out[g1];
            float2 h1;
            h1.x = tanhf(z1.x + acc[nt][2]);
            h1.y = tanhf(z1.y + acc[nt][3]);
            *(float2*)&out[g1] = h1;
            hs[(grp + 8) * 260 + col] = h1.x;
            hs[(grp + 8) * 260 + col + 1] = h1.y;
        }
        __syncthreads();   // hs fully updated before next step's A-frag reads
    }
}

// ---------------- launch ----------------

extern "C" void kernel_launch(void* const* d_in, const int* in_sizes, int n_in,
                              void* d_out, int out_size)
{
    const float* x  = (const float*)d_in[0];   // [B, S, DI]
    const float* Wx = (const float*)d_in[1];   // [S, DI, DO]
    const float* Wh = (const float*)d_in[2];   // [S, DO, DO]
    float* out = (float*)d_out;                // [B, S, DO]

    cudaFuncSetAttribute(rnn_phase1, cudaFuncAttributeMaxDynamicSharedMemorySize, P1_SMEM);
    cudaFuncSetAttribute(rnn_phase2, cudaFuncAttributeMaxDynamicSharedMemorySize, P2_SMEM);

    // Phase 1: Z = batched x @ Wx -> d_out
    dim3 g1(DO_ / 128, B_ / 128, S_);
    rnn_phase1<<<g1, 256, P1_SMEM>>>(x, Wx, out);

    // Phase 2: recurrence over t, batch-partitioned persistent CTAs
    rnn_phase2<<<B_ / 16, 256, P2_SMEM>>>(Wh, out);
}

// round 2
// speedup vs baseline: 1.3164x; 1.3164x over previous
#include <cuda_runtime.h>
#include <cuda_bf16.h>
#include <math.h>

// Problem constants
#define B_  512
#define S_  512
#define DI_ 256
#define DO_ 256

// ---------------- helpers ----------------

__device__ __forceinline__ void cpasync16(void* smem_dst, const void* gsrc) {
    unsigned saddr = (unsigned)__cvta_generic_to_shared(smem_dst);
    asm volatile("cp.async.cg.shared.global [%0], [%1], 16;\n" :: "r"(saddr), "l"(gsrc));
}
__device__ __forceinline__ void cp_commit() {
    asm volatile("cp.async.commit_group;\n");
}
template <int N>
__device__ __forceinline__ void cp_wait() {
    asm volatile("cp.async.wait_group %0;\n" :: "n"(N));
}

__device__ __forceinline__ void mma_tf32(float c[4],
                                         unsigned a0, unsigned a1, unsigned a2, unsigned a3,
                                         unsigned b0, unsigned b1) {
    asm volatile(
        "mma.sync.aligned.m16n8k8.row.col.f32.tf32.tf32.f32 "
        "{%0,%1,%2,%3}, {%4,%5,%6,%7}, {%8,%9}, {%0,%1,%2,%3};\n"
        : "+f"(c[0]), "+f"(c[1]), "+f"(c[2]), "+f"(c[3])
        : "r"(a0), "r"(a1), "r"(a2), "r"(a3), "r"(b0), "r"(b1));
}

__device__ __forceinline__ unsigned f2u(float f) { return __float_as_uint(f); }

__device__ __forceinline__ float fast_tanh(float x) {
    // 1 - 2/(e^{2x}+1); exact at saturation, ~few-ulp elsewhere
    float e = __expf(2.0f * x);
    return 1.0f - __fdividef(2.0f, e + 1.0f);
}

// ---------------- Phase 1: Z[b,t,:] = x[b,t,:] @ Wx[t]  (written into d_out) ----------------
// (unchanged from R1 — passed; phase-1 optimization deferred until it's measured separately)

#define P1_AS  (128 * 36)
#define P1_BS  (32 * 132)
#define P1_SMEM ((2 * P1_AS + 2 * P1_BS) * 4)

__global__ __launch_bounds__(256, 1) void rnn_phase1(
    const float* __restrict__ x, const float* __restrict__ Wx, float* __restrict__ out)
{
    extern __shared__ float sm[];
    float* As[2] = { sm, sm + P1_AS };
    float* Bs[2] = { sm + 2 * P1_AS, sm + 2 * P1_AS + P1_BS };

    const int t      = blockIdx.z;
    const int m_base = blockIdx.y * 128;
    const int n_base = blockIdx.x * 128;
    const int tid    = threadIdx.x;
    const int warp   = tid >> 5, lane = tid & 31;
    const int wm     = warp & 3, wn = warp >> 2;
    const int grp    = lane >> 2, tig = lane & 3;

    float acc[2][8][4];
#pragma unroll
    for (int mt = 0; mt < 2; mt++)
#pragma unroll
        for (int nt = 0; nt < 8; nt++)
#pragma unroll
            for (int i = 0; i < 4; i++) acc[mt][nt][i] = 0.f;

    auto loadA = [&](int kc, int buf) {
#pragma unroll
        for (int j = 0; j < 4; j++) {
            int i = tid + j * 256;
            int r = i >> 3, q = i & 7;
            cpasync16(&As[buf][r * 36 + q * 4],
                      x + ((m_base + r) * S_ + t) * DI_ + kc * 32 + q * 4);
        }
        cp_commit();
    };
    auto loadB = [&](int kc, int buf) {
#pragma unroll
        for (int j = 0; j < 4; j++) {
            int i = tid + j * 256;
            int k = i >> 5, q = i & 31;
            cpasync16(&Bs[buf][k * 132 + q * 4],
                      Wx + t * (DI_ * DO_) + (kc * 32 + k) * DO_ + n_base + q * 4);
        }
        cp_commit();
    };

    loadA(0, 0); loadB(0, 0);
    loadA(1, 1); loadB(1, 1);

    for (int kc = 0; kc < 8; kc++) {
        if (kc < 7) cp_wait<2>(); else cp_wait<0>();
        __syncthreads();
        const int buf = kc & 1;
        const float* A = As[buf];
        const float* Bsm = Bs[buf];
#pragma unroll
        for (int ks = 0; ks < 4; ks++) {
            const int k = ks * 8;
            unsigned a[2][4];
#pragma unroll
            for (int mt = 0; mt < 2; mt++) {
                const int rb = wm * 32 + mt * 16;
                a[mt][0] = f2u(A[(rb + grp)     * 36 + k + tig]);
                a[mt][1] = f2u(A[(rb + grp + 8) * 36 + k + tig]);
                a[mt][2] = f2u(A[(rb + grp)     * 36 + k + 4 + tig]);
                a[mt][3] = f2u(A[(rb + grp + 8) * 36 + k + 4 + tig]);
            }
#pragma unroll
            for (int nt = 0; nt < 8; nt++) {
                const int cb = wn * 64 + nt * 8 + grp;
                unsigned b0 = f2u(Bsm[(k + tig)     * 132 + cb]);
                unsigned b1 = f2u(Bsm[(k + 4 + tig) * 132 + cb]);
#pragma unroll
                for (int mt = 0; mt < 2; mt++)
                    mma_tf32(acc[mt][nt], a[mt][0], a[mt][1], a[mt][2], a[mt][3], b0, b1);
            }
        }
        __syncthreads();
        if (kc + 2 < 8) { loadA(kc + 2, buf); loadB(kc + 2, buf); }
    }

#pragma unroll
    for (int mt = 0; mt < 2; mt++) {
#pragma unroll
        for (int nt = 0; nt < 8; nt++) {
            const int row = m_base + wm * 32 + mt * 16 + grp;
            const int col = n_base + wn * 64 + nt * 8 + 2 * tig;
            const int g0 = (row * S_ + t) * DO_ + col;
            float2 v0; v0.x = acc[mt][nt][0]; v0.y = acc[mt][nt][1];
            *(float2*)&out[g0] = v0;
            const int g1 = ((row + 8) * S_ + t) * DO_ + col;
            float2 v1; v1.x = acc[mt][nt][2]; v1.y = acc[mt][nt][3];
            *(float2*)&out[g1] = v1;
        }
    }
}

// ---------------- Phase 2 v2: transposed recurrence, 64 CTAs x 8 batch rows ----------------
// h_t^T = tanh( Z_t^T + Wh[t]^T @ h_{t-1}^T )
//   mma m16n8k8: M = output cols (256), N = batch rows (8), K = 256.
// Wh streamed as a flat conveyor of 4096 chunks (32 k-rows each) through a 4-buffer
// cp.async pipeline crossing step boundaries; one barrier per chunk.
// 8 warps: warp w owns output cols [w*32, w*32+32) (2 m-tiles of 16).

#define P2_WPAD  260                 // 256-float rows padded to 260 (conflict-free frags)
#define P2_HS    (8 * P2_WPAD)       // h^T as h[batch][k], 8 x 260
#define P2_CHK   32                  // k-rows per chunk
#define P2_WCH   (P2_CHK * P2_WPAD)  // chunk floats
#define P2_NBUF  4
#define P2_SMEM  ((P2_HS + P2_NBUF * P2_WCH) * 4)
#define P2_NCHUNKS (S_ * 8)          // 4096

__global__ __launch_bounds__(256, 1) void rnn_phase2(
    const float* __restrict__ Wh, float* __restrict__ out)
{
    extern __shared__ float sm[];
    float* hs = sm;                  // [8][260]
    float* wb = sm + P2_HS;          // 4 x [32][260]

    const int tid  = threadIdx.x;
    const int warp = tid >> 5, lane = tid & 31;
    const int grp  = lane >> 2, tig = lane & 3;
    const int brow = blockIdx.x * 8;
    const int mbw  = warp * 32;

    // h_{-1} = 0
    for (int i = tid; i < P2_HS; i += 256) hs[i] = 0.f;
    __syncthreads();

    auto loadCh = [&](int c) {
        float* dst = wb + (c & (P2_NBUF - 1)) * P2_WCH;
        const float* src = Wh + (size_t)c * (P2_CHK * DO_);
#pragma unroll
        for (int j = 0; j < 8; j++) {
            int i = tid + j * 256;
            int k = i >> 6, q = i & 63;          // 64 float4 per 256-float row
            cpasync16(&dst[k * P2_WPAD + q * 4], src + k * DO_ + q * 4);
        }
        cp_commit();
    };

    loadCh(0); loadCh(1); loadCh(2);

    float acc[2][4];
    float z[2][4];

    for (int t = 0; t < S_; t++) {
#pragma unroll
        for (int mt = 0; mt < 2; mt++)
#pragma unroll
            for (int i = 0; i < 4; i++) acc[mt][i] = 0.f;

        for (int kc = 0; kc < 8; kc++) {
            const int idx = t * 8 + kc;
            cp_wait<2>();            // oldest outstanding chunk (idx) has landed
            __syncthreads();         // data visible to all warps; buf (idx-1)&3 free
            if (idx + 3 < P2_NCHUNKS) loadCh(idx + 3);
            else cp_commit();        // keep group-count invariant at the tail

            if (kc == 0) {
                // Prefetch Z for this step (independent of h; hidden behind mma)
#pragma unroll
                for (int mt = 0; mt < 2; mt++) {
                    const int col = mbw + mt * 16 + grp;
                    const int r0  = brow + 2 * tig;
                    z[mt][0] = __ldg(&out[((size_t)r0 * S_ + t) * DO_ + col]);
                    z[mt][1] = __ldg(&out[((size_t)(r0 + 1) * S_ + t) * DO_ + col]);
                    z[mt][2] = __ldg(&out[((size_t)r0 * S_ + t) * DO_ + col + 8]);
                    z[mt][3] = __ldg(&out[((size_t)(r0 + 1) * S_ + t) * DO_ + col + 8]);
                }
            }

            const float* W = wb + (idx & (P2_NBUF - 1)) * P2_WCH;
            const int kb = kc * P2_CHK;
#pragma unroll
            for (int ks = 0; ks < 4; ks++) {
                const int k = ks * 8;
                // B-frag: h^T[k][n=batch] -> hs[batch=grp][kb+k+tig]
                unsigned b0 = f2u(hs[grp * P2_WPAD + kb + k + tig]);
                unsigned b1 = f2u(hs[grp * P2_WPAD + kb + k + 4 + tig]);
#pragma unroll
                for (int mt = 0; mt < 2; mt++) {
                    const int mb = mbw + mt * 16;
                    // A-frag: Wh^T[m][k] = Wsm[k][m]
                    unsigned a0 = f2u(W[(k + tig)     * P2_WPAD + mb + grp]);
                    unsigned a1 = f2u(W[(k + tig)     * P2_WPAD + mb + grp + 8]);
                    unsigned a2 = f2u(W[(k + 4 + tig) * P2_WPAD + mb + grp]);
                    unsigned a3 = f2u(W[(k + 4 + tig) * P2_WPAD + mb + grp + 8]);
                    mma_tf32(acc[mt], a0, a1, a2, a3, b0, b1);
                }
            }
        }

        __syncthreads();  // all B-frag reads of h_{t-1} complete before overwrite

        // epilogue: h = tanh(Z + Wh^T h); C[m=outcol][n=batch]
#pragma unroll
        for (int mt = 0; mt < 2; mt++) {
            const int col0 = mbw + mt * 16 + grp;
            const int col1 = col0 + 8;
            const int r0 = brow + 2 * tig;
            const int r1 = r0 + 1;
            const float h0 = fast_tanh(z[mt][0] + acc[mt][0]);  // (col0, r0)
            const float h1 = fast_tanh(z[mt][1] + acc[mt][1]);  // (col0, r1)
            const float h2 = fast_tanh(z[mt][2] + acc[mt][2]);  // (col1, r0)
            const float h3 = fast_tanh(z[mt][3] + acc[mt][3]);  // (col1, r1)
            out[((size_t)r0 * S_ + t) * DO_ + col0] = h0;
            out[((size_t)r1 * S_ + t) * DO_ + col0] = h1;
            out[((size_t)r0 * S_ + t) * DO_ + col1] = h2;
            out[((size_t)r1 * S_ + t) * DO_ + col1] = h3;
            hs[(2 * tig)     * P2_WPAD + col0] = h0;
            hs[(2 * tig + 1) * P2_WPAD + col0] = h1;
            hs[(2 * tig)     * P2_WPAD + col1] = h2;
            hs[(2 * tig + 1) * P2_WPAD + col1] = h3;
        }
        // visibility of new h for next step is covered by the top-of-chunk barrier
    }
}

// ---------------- launch ----------------

extern "C" void kernel_launch(void* const* d_in, const int* in_sizes, int n_in,
                              void* d_out, int out_size)
{
    const float* x  = (const float*)d_in[0];   // [B, S, DI]
    const float* Wx = (const float*)d_in[1];   // [S, DI, DO]
    const float* Wh = (const float*)d_in[2];   // [S, DO, DO]
    float* out = (float*)d_out;                // [B, S, DO]

    cudaFuncSetAttribute(rnn_phase1, cudaFuncAttributeMaxDynamicSharedMemorySize, P1_SMEM);
    cudaFuncSetAttribute(rnn_phase2, cudaFuncAttributeMaxDynamicSharedMemorySize, P2_SMEM);

    dim3 g1(DO_ / 128, B_ / 128, S_);
    rnn_phase1<<<g1, 256, P1_SMEM>>>(x, Wx, out);

    rnn_phase2<<<B_ / 8, 256, P2_SMEM>>>(Wh, out);
}

// round 5
// speedup vs baseline: 2.8633x; 2.1751x over previous
#include <cuda_runtime.h>
#include <cuda_bf16.h>
#include <math.h>
#include <stdint.h>

#define B_  512
#define S_  512
#define DI_ 256
#define DO_ 256

// Packed Wh A-fragments: [g(=t*8+kh*4+c)][wm(8)][ks(4)][mt(2)][lane(32)], one float4 each.
// 4096 groups * 8 * 4 * 2 * 32 = 8,388,608 float4 = 134 MB.
__device__ float4 WhP_g[(size_t)S_ * 8 * 8 * 4 * 2 * 32];

// ---------------- helpers ----------------

__device__ __forceinline__ void cpasync16(void* smem_dst, const void* gsrc) {
    unsigned saddr = (unsigned)__cvta_generic_to_shared(smem_dst);
    asm volatile("cp.async.cg.shared.global [%0], [%1], 16;\n" :: "r"(saddr), "l"(gsrc));
}
__device__ __forceinline__ void cp_commit() { asm volatile("cp.async.commit_group;\n"); }
template <int N> __device__ __forceinline__ void cp_wait() {
    asm volatile("cp.async.wait_group %0;\n" :: "n"(N));
}
__device__ __forceinline__ unsigned f2u(float f) { return __float_as_uint(f); }
__device__ __forceinline__ float fast_tanh(float x) {
    float e = __expf(2.0f * x);
    return 1.0f - __fdividef(2.0f, e + 1.0f);
}
__device__ __forceinline__ uint32_t smem_u32(const void* p) {
    return (uint32_t)__cvta_generic_to_shared(p);
}

__device__ __forceinline__ void mma_tf32(float c[4],
                                         unsigned a0, unsigned a1, unsigned a2, unsigned a3,
                                         unsigned b0, unsigned b1) {
    asm volatile(
        "mma.sync.aligned.m16n8k8.row.col.f32.tf32.tf32.f32 "
        "{%0,%1,%2,%3}, {%4,%5,%6,%7}, {%8,%9}, {%0,%1,%2,%3};\n"
        : "+f"(c[0]), "+f"(c[1]), "+f"(c[2]), "+f"(c[3])
        : "r"(a0), "r"(a1), "r"(a2), "r"(a3), "r"(b0), "r"(b1));
}

#define LDSM_X4(r0, r1, r2, r3, addr) \
    asm volatile("ldmatrix.sync.aligned.m8n8.x4.shared.b16 {%0,%1,%2,%3}, [%4];" \
                 : "=r"(r0), "=r"(r1), "=r"(r2), "=r"(r3) : "r"(addr))

// ---------------- Phase 0: pack Wh into fragment-major layout ----------------
// grid (slab=8, t=512), 256 thr. slab covers k rows [slab*32, slab*32+32).
// A = Wh^T[m][k] = Wh[k][m]; fragment element (wm,ks,mt,lane):
//   v = { A[m0][kk], A[m0+8][kk], A[m0][kk+4], A[m0+8][kk+4] },
//   m0 = wm*32+mt*16+(lane>>2), kk = slab*32+ks*8+(lane&3).

__global__ __launch_bounds__(256, 1) void prepack_wh(const float* __restrict__ Wh)
{
    __shared__ float tile[32 * 260];
    const int slab = blockIdx.x;
    const int t    = blockIdx.y;
    const int tid  = threadIdx.x;
    const float* src = Wh + (size_t)t * (DO_ * DO_) + (size_t)slab * 32 * DO_;

#pragma unroll
    for (int j = 0; j < 8; j++) {
        int idx = tid + j * 256;
        int r = idx >> 6, q = idx & 63;
        *(float4*)&tile[r * 260 + q * 4] = *(const float4*)&src[r * DO_ + q * 4];
    }
    __syncthreads();

    const size_t g = (size_t)t * 8 + slab;
#pragma unroll
    for (int j = 0; j < 8; j++) {
        int idx  = tid + j * 256;                 // 0..2047
        int lane = idx & 31;                      // bits 0-4
        int mt   = (idx >> 5) & 1;                // bit 5
        int ks   = (idx >> 6) & 3;                // bits 6-7
        int wm   = (idx >> 8) & 7;                // bits 8-10
        int kloc = ks * 8 + (lane & 3);
        int m0   = wm * 32 + mt * 16 + (lane >> 2);
        float4 v;
        v.x = tile[kloc * 260 + m0];
        v.y = tile[kloc * 260 + m0 + 8];
        v.z = tile[(kloc + 4) * 260 + m0];
        v.w = tile[(kloc + 4) * 260 + m0 + 8];
        WhP_g[(g * 8 + wm) * 256 + (ks * 2 + mt) * 32 + lane] = v;
    }
}

// ---------------- Phase 1: Z[b,t,:] = x[b,t,:] @ Wx[t]  (2 CTAs/SM) ----------------

#define P1_AS  (128 * 36)
#define P1_BS  (32 * 132)
#define P1_SMEM ((2 * P1_AS + 2 * P1_BS) * 4)

__global__ __launch_bounds__(256, 2) void rnn_phase1(
    const float* __restrict__ x, const float* __restrict__ Wx, float* __restrict__ out)
{
    extern __shared__ float sm[];
    float* As[2] = { sm, sm + P1_AS };
    float* Bs[2] = { sm + 2 * P1_AS, sm + 2 * P1_AS + P1_BS };

    const int t      = blockIdx.z;
    const int m_base = blockIdx.y * 128;
    const int n_base = blockIdx.x * 128;
    const int tid    = threadIdx.x;
    const int warp   = tid >> 5, lane = tid & 31;
    const int wm     = warp & 3, wn = warp >> 2;
    const int grp    = lane >> 2, tig = lane & 3;

    float acc[2][8][4];
#pragma unroll
    for (int mt = 0; mt < 2; mt++)
#pragma unroll
        for (int nt = 0; nt < 8; nt++)
#pragma unroll
            for (int i = 0; i < 4; i++) acc[mt][nt][i] = 0.f;

    auto loadA = [&](int kc, int buf) {
#pragma unroll
        for (int j = 0; j < 4; j++) {
            int i = tid + j * 256;
            int r = i >> 3, q = i & 7;
            cpasync16(&As[buf][r * 36 + q * 4],
                      x + ((m_base + r) * S_ + t) * DI_ + kc * 32 + q * 4);
        }
        cp_commit();
    };
    auto loadB = [&](int kc, int buf) {
#pragma unroll
        for (int j = 0; j < 4; j++) {
            int i = tid + j * 256;
            int k = i >> 5, q = i & 31;
            cpasync16(&Bs[buf][k * 132 + q * 4],
                      Wx + t * (DI_ * DO_) + (kc * 32 + k) * DO_ + n_base + q * 4);
        }
        cp_commit();
    };

    loadA(0, 0); loadB(0, 0);
    loadA(1, 1); loadB(1, 1);

    for (int kc = 0; kc < 8; kc++) {
        if (kc < 7) cp_wait<2>(); else cp_wait<0>();
        __syncthreads();
        const int buf = kc & 1;
        const float* A = As[buf];
        const float* Bsm = Bs[buf];
#pragma unroll
        for (int ks = 0; ks < 4; ks++) {
            const int k = ks * 8;
            unsigned a[2][4];
#pragma unroll
            for (int mt = 0; mt < 2; mt++) {
                const int rb = wm * 32 + mt * 16;
                a[mt][0] = f2u(A[(rb + grp)     * 36 + k + tig]);
                a[mt][1] = f2u(A[(rb + grp + 8) * 36 + k + tig]);
                a[mt][2] = f2u(A[(rb + grp)     * 36 + k + 4 + tig]);
                a[mt][3] = f2u(A[(rb + grp + 8) * 36 + k + 4 + tig]);
            }
#pragma unroll
            for (int nt = 0; nt < 8; nt++) {
                const int cb = wn * 64 + nt * 8 + grp;
                unsigned b0 = f2u(Bsm[(k + tig)     * 132 + cb]);
                unsigned b1 = f2u(Bsm[(k + 4 + tig) * 132 + cb]);
#pragma unroll
                for (int mt = 0; mt < 2; mt++)
                    mma_tf32(acc[mt][nt], a[mt][0], a[mt][1], a[mt][2], a[mt][3], b0, b1);
            }
        }
        __syncthreads();
        if (kc + 2 < 8) { loadA(kc + 2, buf); loadB(kc + 2, buf); }
    }

#pragma unroll
    for (int mt = 0; mt < 2; mt++) {
#pragma unroll
        for (int nt = 0; nt < 8; nt++) {
            const int row = m_base + wm * 32 + mt * 16 + grp;
            const int col = n_base + wn * 64 + nt * 8 + 2 * tig;
            const int g0 = (row * S_ + t) * DO_ + col;
            float2 v0; v0.x = acc[mt][nt][0]; v0.y = acc[mt][nt][1];
            *(float2*)&out[g0] = v0;
            const int g1 = ((row + 8) * S_ + t) * DO_ + col;
            float2 v1; v1.x = acc[mt][nt][2]; v1.y = acc[mt][nt][3];
            *(float2*)&out[g1] = v1;
        }
    }
}

// ---------------- Phase 2 v3: register-streamed Wh, 64 CTAs x 512 threads ----------------
// h_t^T = tanh(Z_t^T + Wh[t]^T @ h_{t-1}^T). Per CTA: N=8 batch rows.
// 16 warps = (kh 2 k-halves) x (wm 8 m-slices of 32 cols, mt=2).
// A-frags: LDG.128 from WhP_g (packed), 2-stage register ring, prefetch s+2.
// B-frags: h in smem [8][260], ldmatrix.x4 (2 per chunk).
// Partial-K exchange via 8KB smem; each k-half does the epilogue for its own mt tile.

#define P2_HPAD 260

__global__ __launch_bounds__(512, 1) void rnn_phase2(float* __restrict__ out)
{
    __shared__ __align__(16) float hs[8 * P2_HPAD];
    __shared__ __align__(16) float4 scr[2][8][32];

    const int tid  = threadIdx.x;
    const int w    = tid >> 5, lane = tid & 31;
    const int grp  = lane >> 2, tig = lane & 3;
    const int kh   = w >> 3, wm = w & 7;
    const int brow = blockIdx.x * 8;
    const int m0   = wm * 32 + kh * 16 + grp;   // epilogue col base (this warp's mt=kh tile)
    const int n0   = 2 * tig;

    for (int i = tid; i < 8 * P2_HPAD; i += 512) hs[i] = 0.f;
    __syncthreads();

    const uint32_t hs_base = smem_u32(hs);
    const uint32_t lm_row  = (uint32_t)((lane & 7) * P2_HPAD + (lane >> 3) * 4) * 4;

    float4 A[2][4][2];

    auto ldA = [&](int s, int st) {
        const int g = ((s >> 2) << 3) | (kh << 2) | (s & 3);
        const size_t base = ((size_t)g * 8 + wm) * 256 + lane;
#pragma unroll
        for (int ks = 0; ks < 4; ks++)
#pragma unroll
            for (int mt = 0; mt < 2; mt++)
                A[st][ks][mt] = __ldg(&WhP_g[base + (ks * 2 + mt) * 32]);
    };

    ldA(0, 0);
    ldA(1, 1);

    float acc[2][4];
    float z[4];
    int s = 0;

    for (int t = 0; t < S_; t++) {
#pragma unroll
        for (int mt = 0; mt < 2; mt++)
#pragma unroll
            for (int i = 0; i < 4; i++) acc[mt][i] = 0.f;

        // Z prefetch for this warp's epilogue tile (independent of h)
        z[0] = __ldg(&out[((size_t)(brow + n0)     * S_ + t) * DO_ + m0]);
        z[1] = __ldg(&out[((size_t)(brow + n0 + 1) * S_ + t) * DO_ + m0]);
        z[2] = __ldg(&out[((size_t)(brow + n0)     * S_ + t) * DO_ + m0 + 8]);
        z[3] = __ldg(&out[((size_t)(brow + n0 + 1) * S_ + t) * DO_ + m0 + 8]);

        for (int c = 0; c < 4; c++) {
            const int st = s & 1;
            const int kb = kh * 128 + c * 32;
            const uint32_t a0 = hs_base + lm_row + (uint32_t)kb * 4;
            uint32_t b0, b1, b2, b3, b4, b5, b6, b7;
            LDSM_X4(b0, b1, b2, b3, a0);
            LDSM_X4(b4, b5, b6, b7, a0 + 64);

            const uint32_t bb[8] = { b0, b1, b2, b3, b4, b5, b6, b7 };
#pragma unroll
            for (int ks = 0; ks < 4; ks++) {
#pragma unroll
                for (int mt = 0; mt < 2; mt++) {
                    const float4 af = A[st][ks][mt];
                    mma_tf32(acc[mt], f2u(af.x), f2u(af.y), f2u(af.z), f2u(af.w),
                             bb[2 * ks], bb[2 * ks + 1]);
                }
            }
            if (s + 2 < 4 * S_) ldA(s + 2, st);
            s++;
        }

        // exchange partial sums for the other mt tile
        if (kh == 0) {
            scr[0][wm][lane] = make_float4(acc[1][0], acc[1][1], acc[1][2], acc[1][3]);
        } else {
            scr[1][wm][lane] = make_float4(acc[0][0], acc[0][1], acc[0][2], acc[0][3]);
        }
        __syncthreads();   // scratch visible; all ldmatrix reads of h_{t-1} done

        const float4 p = scr[kh ^ 1][wm][lane];
        const float h0 = fast_tanh(z[0] + acc[kh][0] + p.x);
        const float h1 = fast_tanh(z[1] + acc[kh][1] + p.y);
        const float h2 = fast_tanh(z[2] + acc[kh][2] + p.z);
        const float h3 = fast_tanh(z[3] + acc[kh][3] + p.w);

        out[((size_t)(brow + n0)     * S_ + t) * DO_ + m0]     = h0;
        out[((size_t)(brow + n0 + 1) * S_ + t) * DO_ + m0]     = h1;
        out[((size_t)(brow + n0)     * S_ + t) * DO_ + m0 + 8] = h2;
        out[((size_t)(brow + n0 + 1) * S_ + t) * DO_ + m0 + 8] = h3;

        hs[n0 * P2_HPAD + m0]           = h0;
        hs[(n0 + 1) * P2_HPAD + m0]     = h1;
        hs[n0 * P2_HPAD + m0 + 8]       = h2;
        hs[(n0 + 1) * P2_HPAD + m0 + 8] = h3;

        __syncthreads();   // new h visible before next step's ldmatrix
    }
}

// ---------------- launch ----------------

extern "C" void kernel_launch(void* const* d_in, const int* in_sizes, int n_in,
                              void* d_out, int out_size)
{
    const float* x  = (const float*)d_in[0];   // [B, S, DI]
    const float* Wx = (const float*)d_in[1];   // [S, DI, DO]
    const float* Wh = (const float*)d_in[2];   // [S, DO, DO]
    float* out = (float*)d_out;                // [B, S, DO]

    cudaFuncSetAttribute(rnn_phase1, cudaFuncAttributeMaxDynamicSharedMemorySize, P1_SMEM);

    prepack_wh<<<dim3(8, S_), 256>>>(Wh);

    dim3 g1(DO_ / 128, B_ / 128, S_);
    rnn_phase1<<<g1, 256, P1_SMEM>>>(x, Wx, out);

    rnn_phase2<<<B_ / 8, 512>>>(out);
}